// round 10
// baseline (speedup 1.0000x reference)
#include <cuda_runtime.h>

// SparseTopKLayer: out = x + ((x*rms)*w)*mask*gamma
//   rms = rsqrt(mean(x^2)+1e-6); mask = |x_norm| >= kth_largest(|x_norm|, k)
// Rank on |x*w| (rms>0 row-constant -> identical ordering).
// One CTA per row, 256 threads, 8 elems/thread.
// SPMD-redundant select: ALL warps compute the scan/classify step on
// identical smem inputs -> select state lives in uniform registers, one
// barrier per round, no publish/read phases. Per-bin min/max fused into the
// histogram insert makes every exit barrier-free. Exact for arbitrary data.

constexpr int D    = 2048;
constexpr int T    = 256;
constexpr int BINS = 128;

// smem layout: [0,256)=cnt[2][128]  [256,512)=mnv[2][128]  [512,768)=mxv[2][128]
#define CNT(p) (sbuf + (p) * BINS)
#define MNV(p) (sbuf + 256 + (p) * BINS)
#define MXV(p) (sbuf + 512 + (p) * BINS)

__device__ __forceinline__ float inv_phi_tail(float q) {
    // Phi^{-1}(1-q), q in (0,0.5]; Abramowitz-Stegun 26.2.23, |err|<4.5e-4
    q = fminf(fmaxf(q, 1e-7f), 0.4999f);
    float s = sqrtf(-2.0f * __logf(q));
    return s - (2.30753f + 0.27061f * s) / (1.0f + s * (0.99229f + 0.04481f * s));
}

__global__ void __launch_bounds__(T, 6) sparse_topk_kernel(
    const float* __restrict__ x,
    const float* __restrict__ w,
    const float* __restrict__ g,
    const int* __restrict__ kptr,
    float* __restrict__ out)
{
    const int row  = blockIdx.x;
    const int t    = threadIdx.x;
    const int lane = t & 31;
    const int wid  = t >> 5;

    __shared__ float red[8];
    __shared__ __align__(16) unsigned sbuf[768];

    // ---- load x,w once; xw in regs; sum of x^2 ----
    const float4* xr = reinterpret_cast<const float4*>(x) + (size_t)row * (D / 4);
    const float4* wv = reinterpret_cast<const float4*>(w);
    float4 xa = xr[t], xb = xr[t + T];
    float4 wa = wv[t], wb = wv[t + T];

    float xv[8] = {xa.x,xa.y,xa.z,xa.w,xb.x,xb.y,xb.z,xb.w};
    float xw[8];
    float ss = 0.0f;
    {
        float wf[8] = {wa.x,wa.y,wa.z,wa.w,wb.x,wb.y,wb.z,wb.w};
        #pragma unroll
        for (int i = 0; i < 8; i++) {
            xw[i] = xv[i] * wf[i];
            ss = fmaf(xv[i], xv[i], ss);
        }
    }
    #pragma unroll
    for (int o = 16; o > 0; o >>= 1)
        ss += __shfl_xor_sync(0xffffffffu, ss, o);
    if (lane == 0) red[wid] = ss;
    // zero all 6 buffers (cnt x2, mnv x2, mxv x2)
    sbuf[t]       = 0u;
    sbuf[256 + t] = 0xFFFFFFFFu;
    sbuf[512 + t] = 0u;
    __syncthreads();

    // ---- EVERY warp: block sum + rms + quantile window (uniform regs) ----
    float bs = 0.0f;
    #pragma unroll
    for (int j = 0; j < 8; j++) bs += red[j];
    const float ms  = bs * (1.0f / (float)D);
    const float rms = rsqrtf(ms + 1e-6f);
    const float sigma = sqrtf(ms);            // |w|~1 heuristic (window only)
    const int k = *kptr;
    float t1 = inv_phi_tail((float)(k + 96) * (0.5f / (float)D));
    float t2 = inv_phi_tail((float)(k - 96 > 1 ? k - 96 : 1) * (0.5f / (float)D));
    unsigned lo_ = (t1 > 0.0f) ? __float_as_uint(t1 * sigma) : 0u;
    unsigned hq  = __float_as_uint(fmaxf(t2, 0.0f) * sigma);
    if (hq <= lo_) hq = lo_ + 1u;
    unsigned wsoft = hq - lo_;
    unsigned hi_ = 0x80000000u;                // open top; tail folds into bin 127
    int s = (wsoft > (unsigned)BINS) ? (25 - __clz(wsoft - 1u)) : 0;
    int r = k, p = 0;

    // ---- adaptive-window select: 1 barrier per round, barrier-free exits ----
    unsigned thr = 0u;
    while (true) {
        const unsigned range = hi_ - lo_;
        unsigned* hc = CNT(p);
        unsigned* hn = MNV(p);
        unsigned* hx = MXV(p);
        #pragma unroll
        for (int i = 0; i < 8; i++) {
            unsigned ub = __float_as_uint(xw[i]) & 0x7FFFFFFFu;
            unsigned d = ub - lo_;
            if (d < range) {
                unsigned b = d >> s;
                if (b > (unsigned)(BINS - 1)) b = BINS - 1;   // tail bin
                atomicAdd(&hc[b], 1u);
                atomicMin(&hn[b], ub);
                atomicMax(&hx[b], ub);
            }
        }
        // zero the other buffer set for a possible next round
        if (t < BINS) {
            CNT(p ^ 1)[t] = 0u;
            MNV(p ^ 1)[t] = 0xFFFFFFFFu;
        } else {
            MXV(p ^ 1)[t - BINS] = 0u;
        }
        __syncthreads();

        // every warp scans the identical histogram -> identical decision
        uint4 hv = *reinterpret_cast<const uint4*>(&hc[lane * 4]);
        unsigned hr[4] = {hv.x, hv.y, hv.z, hv.w};
        unsigned bsum = hr[0] + hr[1] + hr[2] + hr[3];
        unsigned S = bsum;
        #pragma unroll
        for (int o = 1; o < 32; o <<= 1) {
            unsigned v = __shfl_down_sync(0xffffffffu, S, o);
            if (lane + o < 32) S += v;
        }
        const unsigned total = __shfl_sync(0xffffffffu, S, 0);

        if ((unsigned)r > total) {              // threshold below window
            unsigned nr = lo_;                  // new window [0, lo)
            hi_ = lo_; lo_ = 0u;
            s = (nr > (unsigned)BINS) ? (25 - __clz(nr - 1u)) : 0;
            r -= (int)total;
            p ^= 1;
            continue;
        }

        unsigned suf = S - bsum;                // count in strictly-higher lanes
        int bj = -1; unsigned cb = 0, abv = 0;
        #pragma unroll
        for (int j = 3; j >= 0; j--) {
            unsigned ns = suf + hr[j];
            if (suf < (unsigned)r && ns >= (unsigned)r) { bj = j; cb = hr[j]; abv = suf; }
            suf = ns;
        }
        unsigned bal = __ballot_sync(0xffffffffu, bj >= 0);
        int src = __ffs(bal) - 1;
        unsigned B = __shfl_sync(0xffffffffu, (unsigned)(lane * 4 + bj), src);
        cb  = __shfl_sync(0xffffffffu, cb, src);
        abv = __shfl_sync(0xffffffffu, abv, src);

        int r2 = r - (int)abv;
        unsigned nlo = lo_ + (B << s);
        unsigned nhi = (B >= (unsigned)(BINS - 1)) ? hi_ : (lo_ + ((B + 1u) << s));
        if (nhi > hi_) nhi = hi_;
        unsigned nrange = nhi - nlo;

        if (nrange <= 1u)  { thr = nlo;    break; }
        if ((int)cb == r2) { thr = hn[B];  break; }   // min of bucket (broadcast LDS)
        if (r2 == 1)       { thr = hx[B];  break; }   // max of bucket

        lo_ = nlo; hi_ = nhi; r = r2;
        s = (nrange > (unsigned)BINS) ? (25 - __clz(nrange - 1u)) : 0;
        p ^= 1;
    }

    // ---- epilogue: out = x + (xw*rms)*g where |xw| >= thr ----
    const float4* gv = reinterpret_cast<const float4*>(g);
    float4 ga = gv[t], gb = gv[t + T];
    float gf[8] = {ga.x,ga.y,ga.z,ga.w,gb.x,gb.y,gb.z,gb.w};
    const float thrf = __uint_as_float(thr);

    float fo[8];
    #pragma unroll
    for (int i = 0; i < 8; i++) {
        float keep = (fabsf(xw[i]) >= thrf) ? (rms * gf[i]) : 0.0f;
        fo[i] = fmaf(xw[i], keep, xv[i]);
    }
    float4* orow = reinterpret_cast<float4*>(out) + (size_t)row * (D / 4);
    orow[t]     = make_float4(fo[0], fo[1], fo[2], fo[3]);
    orow[t + T] = make_float4(fo[4], fo[5], fo[6], fo[7]);
}

extern "C" void kernel_launch(void* const* d_in, const int* in_sizes, int n_in,
                              void* d_out, int out_size)
{
    const float* x = (const float*)d_in[0];
    const float* w = (const float*)d_in[1];
    const float* g = (const float*)d_in[2];
    const int*   k = (const int*)d_in[3];

    int N = in_sizes[0] / D;   // 32768 rows
    sparse_topk_kernel<<<N, T>>>(x, w, g, k, (float*)d_out);
}